// round 10
// baseline (speedup 1.0000x reference)
#include <cuda_runtime.h>
#include <cuda_fp16.h>
#include <cstdint>

#define N_NODES 100000
#define N_EDGES 600000
#define FEAT    128
#define N_GRAPHS 100
#define BN_EPS  1e-5f
#define SLOTS   64

typedef unsigned long long ull;
typedef unsigned int uint;

// ---------------- scratch (device globals: no allocations allowed) ----------
// INVARIANT: g_cnt is all-zero at every kernel_launch entry (zero-init at load,
// reset by k_gather after each use).
__device__ uint  g_Z[(size_t)N_NODES * 64];       // Z = (h*norm)@W, half2-packed
__device__ uint  g_Y[(size_t)N_NODES * 64];       // post-relu activations, half2-packed
__device__ int   g_cnt[N_NODES];                  // per-node in-degree
__device__ int   g_slot[(size_t)N_NODES * SLOTS]; // per-node src lists (padded)
__device__ float g_sum[FEAT];
__device__ float g_sumsq[FEAT];

// ---------------- helpers ---------------------------------------------------
__device__ __forceinline__ ull pk(float x) {
    ull r; asm("mov.b64 %0, {%1, %1};" : "=l"(r) : "f"(x)); return r;
}
__device__ __forceinline__ void ffma2(ull& d, ull a, ull b) {
    asm("fma.rn.f32x2 %0, %1, %2, %3;" : "=l"(d) : "l"(a), "l"(b), "l"(d));
}
__device__ __forceinline__ float2 up(ull v) {
    float2 p; asm("mov.b64 {%0, %1}, %2;" : "=f"(p.x), "=f"(p.y) : "l"(v)); return p;
}

// ---------------- K0: edge-list build + zeroing (phis, BN sums) -------------
// 300 blocks x 256 threads; 2000 edges per block. Blocks 0..50 also zero the
// 13056 floats of phis/g_sum/g_sumsq. g_cnt pre-zeroed by invariant.
#define BUILD_BLKS 300
#define EPB (N_EDGES / BUILD_BLKS)            // 2000
#define NZERO2 (N_GRAPHS * FEAT + 2 * FEAT)   // 13056
__global__ void __launch_bounds__(256)
k_build(const int* __restrict__ src, const int* __restrict__ dst,
        float* __restrict__ phis) {
    int tid = threadIdx.x;
    int z = blockIdx.x * 256 + tid;
    if (z < N_GRAPHS * FEAT)      phis[z] = 0.f;
    else if (z < NZERO2) {
        int q = z - N_GRAPHS * FEAT;
        if (q < FEAT) g_sum[q] = 0.f; else g_sumsq[q - FEAT] = 0.f;
    }
    int e_end = (blockIdx.x + 1) * EPB;
    for (int e = blockIdx.x * EPB + tid; e < e_end; e += 256) {
        int d = __ldg(&dst[e]);
        int s = __ldg(&src[e]);
        int pos = atomicAdd(&g_cnt[d], 1);
        g_slot[(size_t)d * SLOTS + pos] = s;
    }
}

// ---------------- K1: Z = (h*norm) @ W  (fp16 A-tile, f32x2 FMA) ------------
// 256 threads = 8 warps; tile 128x128, K=128 full. A tile fp16 (32KB) + W tile
// fp32 (64KB) = 96KB -> 2 CTAs/SM (4 warps/SMSP hides LDS latency).
// Warp w: cols 16w..16w+15 (broadcast W). Lane l: rows 4l..4l+3.
__global__ void __launch_bounds__(256, 2)
k_gemm(const float* __restrict__ h, const float* __restrict__ norm,
       const float* __restrict__ Wg) {
    extern __shared__ char smraw[];
    __half* Ah = (__half*)smraw;                    // [k][m] halves, stride 128
    float*  Ws = (float*)(smraw + 32768);           // [k][c] fp32,  stride 128
    int tid = threadIdx.x;
    int rowbase = blockIdx.x * 128;

    // --- A tile: transpose to k-major, scale by norm, convert to fp16 ---
    {
        int r = tid & 127, halfsel = tid >> 7;
        int gr = rowbase + r;
        bool ok = (gr < N_NODES);
        float nm = ok ? __ldg(&norm[gr]) : 0.f;
        const float4* arow = (const float4*)(h + (size_t)gr * FEAT);
        #pragma unroll
        for (int j = 0; j < 16; j++) {
            int k = halfsel * 64 + j * 4;
            float4 v = ok ? __ldg(&arow[k >> 2]) : make_float4(0.f, 0.f, 0.f, 0.f);
            Ah[(k + 0) * 128 + r] = __float2half_rn(v.x * nm);
            Ah[(k + 1) * 128 + r] = __float2half_rn(v.y * nm);
            Ah[(k + 2) * 128 + r] = __float2half_rn(v.z * nm);
            Ah[(k + 3) * 128 + r] = __float2half_rn(v.w * nm);
        }
    }
    // --- W tile (coalesced fp32) ---
    #pragma unroll
    for (int it = 0; it < 16; it++) {
        int g = tid + 256 * it;            // float4 index, 4096 total
        int k = g >> 5, c = (g & 31) * 4;
        *(float4*)&Ws[k * 128 + c] = __ldg(&((const float4*)Wg)[g]);
    }
    __syncthreads();

    int w = tid >> 5, lane = tid & 31;
    int c0 = w * 16, r0 = lane * 4;

    ull acc[32];
    #pragma unroll
    for (int i = 0; i < 32; i++) acc[i] = 0ull;

    #pragma unroll 4
    for (int k = 0; k < 128; k++) {
        uint2 ah = *(const uint2*)(Ah + k * 128 + r0);   // rows r0..r0+3, LDS.64
        float2 f01 = __half22float2(*(__half2*)&ah.x);
        float2 f23 = __half22float2(*(__half2*)&ah.y);
        ull ad[4] = {pk(f01.x), pk(f01.y), pk(f23.x), pk(f23.y)};
        const ull* wp = (const ull*)&Ws[k * 128 + c0];   // broadcast
        ull wd[8];
        #pragma unroll
        for (int c2 = 0; c2 < 8; c2++) wd[c2] = wp[c2];
        #pragma unroll
        for (int r = 0; r < 4; r++)
            #pragma unroll
            for (int c2 = 0; c2 < 8; c2++)
                ffma2(acc[r * 8 + c2], ad[r], wd[c2]);
    }

    // --- store Z rows as half2 ---
    #pragma unroll
    for (int r = 0; r < 4; r++) {
        int row = rowbase + r0 + r;
        if (row < N_NODES) {
            uint st[8];
            #pragma unroll
            for (int c2 = 0; c2 < 8; c2++) {
                float2 p = up(acc[r * 8 + c2]);
                __half2 hv = __floats2half2_rn(p.x, p.y);   // low = even col
                st[c2] = *(uint*)&hv;
            }
            uint* zr = g_Z + (size_t)row * 64 + c0 / 2;
            ((uint4*)zr)[0] = make_uint4(st[0], st[1], st[2], st[3]);
            ((uint4*)zr)[1] = make_uint4(st[4], st[5], st[6], st[7]);
        }
    }
}

// ---------------- K2: Y[v] = relu(norm[v]*sum_nbr Z[s] + b), BN stats -------
// One warp handles a PAIR of nodes; resets g_cnt to 0 after reading (invariant).
#define GBLK 2048
__device__ __forceinline__ void acc_z(float4& a, int s, int lane) {
    uint2 q = __ldg(&((const uint2*)(g_Z + (size_t)s * 64))[lane]);
    float2 f0 = __half22float2(*(__half2*)&q.x);
    float2 f1 = __half22float2(*(__half2*)&q.y);
    a.x += f0.x; a.y += f0.y; a.z += f1.x; a.w += f1.y;
}
__global__ void __launch_bounds__(256, 6)
k_gather(const float* __restrict__ norm, const float* __restrict__ bg) {
    __shared__ float S1[8 * 128];
    __shared__ float S2[8 * 128];
    int lane = threadIdx.x & 31;
    int wid  = threadIdx.x >> 5;
    int gw   = blockIdx.x * 8 + wid;
    const int nw = GBLK * 8;

    float4 bv = __ldg(&((const float4*)bg)[lane]);
    float4 cs = make_float4(0.f, 0.f, 0.f, 0.f);
    float4 cq = make_float4(0.f, 0.f, 0.f, 0.f);

    for (int v0 = gw * 2; v0 < N_NODES; v0 += nw * 2) {
        int v1 = v0 + 1;                       // N_NODES even -> always valid
        int c0 = g_cnt[v0], c1 = g_cnt[v1];
        // reset for next kernel_launch call (maintains the zero invariant)
        if (lane == 0) g_cnt[v0] = 0;
        if (lane == 1) g_cnt[v1] = 0;
        const int* sl0 = g_slot + (size_t)v0 * SLOTS;
        const int* sl1 = g_slot + (size_t)v1 * SLOTS;
        int ms0 = (lane < c0) ? __ldg(&sl0[lane]) : 0;
        int ms1 = (lane < c1) ? __ldg(&sl1[lane]) : 0;

        float4 a0 = make_float4(0.f, 0.f, 0.f, 0.f);
        float4 a1 = make_float4(0.f, 0.f, 0.f, 0.f);
        int cc0 = min(c0, 32), cc1 = min(c1, 32);
        int m = max(cc0, cc1);
        #pragma unroll 4
        for (int i = 0; i < m; i++) {
            if (i < cc0) { int s = __shfl_sync(0xffffffffu, ms0, i); acc_z(a0, s, lane); }
            if (i < cc1) { int s = __shfl_sync(0xffffffffu, ms1, i); acc_z(a1, s, lane); }
        }
        for (int i = 32; i < c0; i++) { int s = __ldg(&sl0[i]); acc_z(a0, s, lane); }
        for (int i = 32; i < c1; i++) { int s = __ldg(&sl1[i]); acc_z(a1, s, lane); }

        float n0 = __ldg(&norm[v0]);
        float n1 = __ldg(&norm[v1]);
        float4 y0, y1;
        y0.x = fmaxf(a0.x * n0 + bv.x, 0.f); y0.y = fmaxf(a0.y * n0 + bv.y, 0.f);
        y0.z = fmaxf(a0.z * n0 + bv.z, 0.f); y0.w = fmaxf(a0.w * n0 + bv.w, 0.f);
        y1.x = fmaxf(a1.x * n1 + bv.x, 0.f); y1.y = fmaxf(a1.y * n1 + bv.y, 0.f);
        y1.z = fmaxf(a1.z * n1 + bv.z, 0.f); y1.w = fmaxf(a1.w * n1 + bv.w, 0.f);
        // store Y as half2 pairs
        {
            __half2 p0 = __floats2half2_rn(y0.x, y0.y);
            __half2 p1 = __floats2half2_rn(y0.z, y0.w);
            ((uint2*)(g_Y + (size_t)v0 * 64))[lane] = make_uint2(*(uint*)&p0, *(uint*)&p1);
            __half2 q0 = __floats2half2_rn(y1.x, y1.y);
            __half2 q1 = __floats2half2_rn(y1.z, y1.w);
            ((uint2*)(g_Y + (size_t)v1 * 64))[lane] = make_uint2(*(uint*)&q0, *(uint*)&q1);
        }
        cs.x += y0.x + y1.x; cs.y += y0.y + y1.y;
        cs.z += y0.z + y1.z; cs.w += y0.w + y1.w;
        cq.x += y0.x * y0.x + y1.x * y1.x; cq.y += y0.y * y0.y + y1.y * y1.y;
        cq.z += y0.z * y0.z + y1.z * y1.z; cq.w += y0.w * y0.w + y1.w * y1.w;
    }

    *(float4*)&S1[wid * 128 + lane * 4] = cs;
    *(float4*)&S2[wid * 128 + lane * 4] = cq;
    __syncthreads();
    int tid = threadIdx.x;
    if (tid < 128) {
        float s = 0.f, q = 0.f;
        #pragma unroll
        for (int y = 0; y < 8; y++) { s += S1[y * 128 + tid]; q += S2[y * 128 + tid]; }
        atomicAdd(&g_sum[tid], s);
        atomicAdd(&g_sumsq[tid], q);
    }
}

// ---------------- K3: BN-finalize (per-warp) + apply + pooled segment sum ---
#define OCHUNK 64
__global__ void __launch_bounds__(256)
k_out(const int* __restrict__ gid, const float* __restrict__ gamma,
      const float* __restrict__ beta, float* __restrict__ xout,
      float* __restrict__ phis) {
    int lane = threadIdx.x & 31;
    int wid  = threadIdx.x >> 5;
    int chunk = blockIdx.x * 8 + wid;
    int r0 = chunk * OCHUNK;
    if (r0 >= N_NODES) return;
    int rend = min(r0 + OCHUNK, N_NODES);

    // recompute scale/shift locally (tiny, L2-cached)
    float4 s1 = *(const float4*)&g_sum[lane * 4];
    float4 s2 = *(const float4*)&g_sumsq[lane * 4];
    float4 gm = __ldg(&((const float4*)gamma)[lane]);
    float4 bt = __ldg(&((const float4*)beta)[lane]);
    const float inv = 1.f / N_NODES;
    float4 sc, sh;
    {
        float m, v;
        m = s1.x * inv; v = s2.x * inv - m * m; sc.x = gm.x * rsqrtf(v + BN_EPS); sh.x = bt.x - m * sc.x;
        m = s1.y * inv; v = s2.y * inv - m * m; sc.y = gm.y * rsqrtf(v + BN_EPS); sh.y = bt.y - m * sc.y;
        m = s1.z * inv; v = s2.z * inv - m * m; sc.z = gm.z * rsqrtf(v + BN_EPS); sh.z = bt.z - m * sc.z;
        m = s1.w * inv; v = s2.w * inv - m * m; sc.w = gm.w * rsqrtf(v + BN_EPS); sh.w = bt.w - m * sc.w;
    }

    float4 acc = make_float4(0.f, 0.f, 0.f, 0.f);
    int gcur = __ldg(&gid[r0]);

    #pragma unroll 4
    for (int r = r0; r < rend; r++) {
        int g = __ldg(&gid[r]);
        uint2 q = ((const uint2*)(g_Y + (size_t)r * 64))[lane];
        float2 f0 = __half22float2(*(__half2*)&q.x);
        float2 f1 = __half22float2(*(__half2*)&q.y);
        float4 v;
        v.x = f0.x * sc.x + sh.x; v.y = f0.y * sc.y + sh.y;
        v.z = f1.x * sc.z + sh.z; v.w = f1.y * sc.w + sh.w;
        ((float4*)(xout + (size_t)r * FEAT))[lane] = v;
        if (g != gcur) {
            float* pp = phis + (size_t)gcur * FEAT + lane * 4;
            atomicAdd(pp + 0, acc.x); atomicAdd(pp + 1, acc.y);
            atomicAdd(pp + 2, acc.z); atomicAdd(pp + 3, acc.w);
            acc = make_float4(0.f, 0.f, 0.f, 0.f);
            gcur = g;
        }
        acc.x += v.x; acc.y += v.y; acc.z += v.z; acc.w += v.w;
    }
    float* pp = phis + (size_t)gcur * FEAT + lane * 4;
    atomicAdd(pp + 0, acc.x); atomicAdd(pp + 1, acc.y);
    atomicAdd(pp + 2, acc.z); atomicAdd(pp + 3, acc.w);
}

// ---------------- launch -----------------------------------------------------
extern "C" void kernel_launch(void* const* d_in, const int* in_sizes, int n_in,
                              void* d_out, int out_size) {
    const float* h     = (const float*)d_in[0];
    const float* norm  = (const float*)d_in[1];
    const float* W     = (const float*)d_in[2];
    const float* b     = (const float*)d_in[3];
    const float* gamma = (const float*)d_in[4];
    const float* beta  = (const float*)d_in[5];
    const int*   src   = (const int*)d_in[6];
    const int*   dst   = (const int*)d_in[7];
    const int*   gid   = (const int*)d_in[8];
    float* xout = (float*)d_out;
    float* phis = xout + (size_t)N_NODES * FEAT;

    const int smem_gemm = 32768 + 65536;   // 96 KB -> 2 CTAs/SM
    cudaFuncSetAttribute(k_gemm, cudaFuncAttributeMaxDynamicSharedMemorySize, smem_gemm);

    k_build<<<BUILD_BLKS, 256>>>(src, dst, phis);
    k_gemm<<<(N_NODES + 127) / 128, 256, smem_gemm>>>(h, norm, W);
    k_gather<<<GBLK, 256>>>(norm, b);
    k_out<<<(N_NODES + OCHUNK * 8 - 1) / (OCHUNK * 8), 256>>>(gid, gamma, beta, xout, phis);
}

// round 11
// speedup vs baseline: 1.0931x; 1.0931x over previous
#include <cuda_runtime.h>
#include <cuda_fp16.h>
#include <cstdint>

#define N_NODES 100000
#define N_EDGES 600000
#define FEAT    128
#define N_GRAPHS 100
#define BN_EPS  1e-5f
#define SLOTS   64

typedef unsigned long long ull;
typedef unsigned int uint;

// ---------------- scratch (device globals: no allocations allowed) ----------
// INVARIANT: g_cnt is all-zero at every kernel_launch entry (zero-init at load,
// reset by k_gather after each use).
__device__ uint  g_Z[(size_t)N_NODES * 64];       // Z = (h*norm)@W, half2-packed
__device__ uint  g_Y[(size_t)N_NODES * 64];       // post-relu activations, half2-packed
__device__ int   g_cnt[N_NODES];                  // per-node in-degree
__device__ int   g_slot[(size_t)N_NODES * SLOTS]; // per-node src lists (padded)
__device__ float g_sum[FEAT];
__device__ float g_sumsq[FEAT];

// ---------------- helpers ---------------------------------------------------
__device__ __forceinline__ ull pk(float x) {
    ull r; asm("mov.b64 %0, {%1, %1};" : "=l"(r) : "f"(x)); return r;
}
__device__ __forceinline__ void ffma2(ull& d, ull a, ull b) {
    asm("fma.rn.f32x2 %0, %1, %2, %3;" : "=l"(d) : "l"(a), "l"(b), "l"(d));
}
__device__ __forceinline__ float2 up(ull v) {
    float2 p; asm("mov.b64 {%0, %1}, %2;" : "=f"(p.x), "=f"(p.y) : "l"(v)); return p;
}

// ---------------- K0: edge-list build + zeroing (phis, BN sums) -------------
// 300 blocks x 256 threads; 2000 edges per block. Blocks 0..50 also zero the
// 13056 floats of phis/g_sum/g_sumsq. g_cnt pre-zeroed by invariant.
#define BUILD_BLKS 300
#define EPB (N_EDGES / BUILD_BLKS)            // 2000
#define NZERO2 (N_GRAPHS * FEAT + 2 * FEAT)   // 13056
__global__ void __launch_bounds__(256)
k_build(const int* __restrict__ src, const int* __restrict__ dst,
        float* __restrict__ phis) {
    int tid = threadIdx.x;
    int z = blockIdx.x * 256 + tid;
    if (z < N_GRAPHS * FEAT)      phis[z] = 0.f;
    else if (z < NZERO2) {
        int q = z - N_GRAPHS * FEAT;
        if (q < FEAT) g_sum[q] = 0.f; else g_sumsq[q - FEAT] = 0.f;
    }
    int e_end = (blockIdx.x + 1) * EPB;
    for (int e = blockIdx.x * EPB + tid; e < e_end; e += 256) {
        int d = __ldg(&dst[e]);
        int s = __ldg(&src[e]);
        int pos = atomicAdd(&g_cnt[d], 1);
        g_slot[(size_t)d * SLOTS + pos] = s;
    }
}

// ---------------- K1: Z = (h*norm) @ W  (fp32 tiles, f32x2 FMA) -------------
// R7-exact GEMM: 256 threads = 8 warps; tile 128x128, K=128 full; 131KB smem.
// Warp w: cols 16w..16w+15 (broadcast W). Lane l: rows 4l..4l+3.
__global__ void __launch_bounds__(256, 1)
k_gemm(const float* __restrict__ h, const float* __restrict__ norm,
       const float* __restrict__ Wg) {
    extern __shared__ float sm[];
    float* As = sm;             // [k][m], stride 128
    float* Ws = sm + 16384;     // [k][c], stride 128
    int tid = threadIdx.x;
    int rowbase = blockIdx.x * 128;

    {
        int r = tid & 127, half = tid >> 7;
        int gr = rowbase + r;
        bool ok = (gr < N_NODES);
        float nm = ok ? __ldg(&norm[gr]) : 0.f;
        const float4* arow = (const float4*)(h + (size_t)gr * FEAT);
        #pragma unroll
        for (int j = 0; j < 16; j++) {
            int k = half * 64 + j * 4;
            float4 v = ok ? __ldg(&arow[k >> 2]) : make_float4(0.f, 0.f, 0.f, 0.f);
            As[(k + 0) * 128 + r] = v.x * nm;
            As[(k + 1) * 128 + r] = v.y * nm;
            As[(k + 2) * 128 + r] = v.z * nm;
            As[(k + 3) * 128 + r] = v.w * nm;
        }
    }
    #pragma unroll
    for (int it = 0; it < 16; it++) {
        int g = tid + 256 * it;            // float4 index, 4096 total
        int k = g >> 5, c = (g & 31) * 4;
        *(float4*)&Ws[k * 128 + c] = __ldg(&((const float4*)Wg)[g]);
    }
    __syncthreads();

    int w = tid >> 5, lane = tid & 31;
    int c0 = w * 16, r0 = lane * 4;

    ull acc[32];
    #pragma unroll
    for (int i = 0; i < 32; i++) acc[i] = 0ull;

    #pragma unroll 4
    for (int k = 0; k < 128; k++) {
        float4 av = *(const float4*)&As[k * 128 + r0];
        ull ad[4] = {pk(av.x), pk(av.y), pk(av.z), pk(av.w)};
        const ull* wp = (const ull*)&Ws[k * 128 + c0];
        ull wd[8];
        #pragma unroll
        for (int c2 = 0; c2 < 8; c2++) wd[c2] = wp[c2];
        #pragma unroll
        for (int r = 0; r < 4; r++)
            #pragma unroll
            for (int c2 = 0; c2 < 8; c2++)
                ffma2(acc[r * 8 + c2], ad[r], wd[c2]);
    }

    // store Z rows as half2
    #pragma unroll
    for (int r = 0; r < 4; r++) {
        int row = rowbase + r0 + r;
        if (row < N_NODES) {
            uint st[8];
            #pragma unroll
            for (int c2 = 0; c2 < 8; c2++) {
                float2 p = up(acc[r * 8 + c2]);
                __half2 hv = __floats2half2_rn(p.x, p.y);   // low = even col
                st[c2] = *(uint*)&hv;
            }
            uint* zr = g_Z + (size_t)row * 64 + c0 / 2;
            ((uint4*)zr)[0] = make_uint4(st[0], st[1], st[2], st[3]);
            ((uint4*)zr)[1] = make_uint4(st[4], st[5], st[6], st[7]);
        }
    }
}

// ---------------- K2: Y[v] = relu(norm[v]*sum_nbr Z[s] + b), BN stats -------
// One warp handles a PAIR of nodes; resets g_cnt to 0 after reading (invariant).
#define GBLK 2048
__device__ __forceinline__ void acc_z(float4& a, int s, int lane) {
    uint2 q = __ldg(&((const uint2*)(g_Z + (size_t)s * 64))[lane]);
    float2 f0 = __half22float2(*(__half2*)&q.x);
    float2 f1 = __half22float2(*(__half2*)&q.y);
    a.x += f0.x; a.y += f0.y; a.z += f1.x; a.w += f1.y;
}
__global__ void __launch_bounds__(256, 6)
k_gather(const float* __restrict__ norm, const float* __restrict__ bg) {
    __shared__ float S1[8 * 128];
    __shared__ float S2[8 * 128];
    int lane = threadIdx.x & 31;
    int wid  = threadIdx.x >> 5;
    int gw   = blockIdx.x * 8 + wid;
    const int nw = GBLK * 8;

    float4 bv = __ldg(&((const float4*)bg)[lane]);
    float4 cs = make_float4(0.f, 0.f, 0.f, 0.f);
    float4 cq = make_float4(0.f, 0.f, 0.f, 0.f);

    for (int v0 = gw * 2; v0 < N_NODES; v0 += nw * 2) {
        int v1 = v0 + 1;                       // N_NODES even -> always valid
        int c0 = g_cnt[v0], c1 = g_cnt[v1];
        // reset for next kernel_launch call (maintains the zero invariant)
        if (lane == 0) g_cnt[v0] = 0;
        if (lane == 1) g_cnt[v1] = 0;
        const int* sl0 = g_slot + (size_t)v0 * SLOTS;
        const int* sl1 = g_slot + (size_t)v1 * SLOTS;
        int ms0 = (lane < c0) ? __ldg(&sl0[lane]) : 0;
        int ms1 = (lane < c1) ? __ldg(&sl1[lane]) : 0;

        float4 a0 = make_float4(0.f, 0.f, 0.f, 0.f);
        float4 a1 = make_float4(0.f, 0.f, 0.f, 0.f);
        int cc0 = min(c0, 32), cc1 = min(c1, 32);
        int m = max(cc0, cc1);
        #pragma unroll 4
        for (int i = 0; i < m; i++) {
            if (i < cc0) { int s = __shfl_sync(0xffffffffu, ms0, i); acc_z(a0, s, lane); }
            if (i < cc1) { int s = __shfl_sync(0xffffffffu, ms1, i); acc_z(a1, s, lane); }
        }
        for (int i = 32; i < c0; i++) { int s = __ldg(&sl0[i]); acc_z(a0, s, lane); }
        for (int i = 32; i < c1; i++) { int s = __ldg(&sl1[i]); acc_z(a1, s, lane); }

        float n0 = __ldg(&norm[v0]);
        float n1 = __ldg(&norm[v1]);
        float4 y0, y1;
        y0.x = fmaxf(a0.x * n0 + bv.x, 0.f); y0.y = fmaxf(a0.y * n0 + bv.y, 0.f);
        y0.z = fmaxf(a0.z * n0 + bv.z, 0.f); y0.w = fmaxf(a0.w * n0 + bv.w, 0.f);
        y1.x = fmaxf(a1.x * n1 + bv.x, 0.f); y1.y = fmaxf(a1.y * n1 + bv.y, 0.f);
        y1.z = fmaxf(a1.z * n1 + bv.z, 0.f); y1.w = fmaxf(a1.w * n1 + bv.w, 0.f);
        // store Y as half2 pairs
        {
            __half2 p0 = __floats2half2_rn(y0.x, y0.y);
            __half2 p1 = __floats2half2_rn(y0.z, y0.w);
            ((uint2*)(g_Y + (size_t)v0 * 64))[lane] = make_uint2(*(uint*)&p0, *(uint*)&p1);
            __half2 q0 = __floats2half2_rn(y1.x, y1.y);
            __half2 q1 = __floats2half2_rn(y1.z, y1.w);
            ((uint2*)(g_Y + (size_t)v1 * 64))[lane] = make_uint2(*(uint*)&q0, *(uint*)&q1);
        }
        cs.x += y0.x + y1.x; cs.y += y0.y + y1.y;
        cs.z += y0.z + y1.z; cs.w += y0.w + y1.w;
        cq.x += y0.x * y0.x + y1.x * y1.x; cq.y += y0.y * y0.y + y1.y * y1.y;
        cq.z += y0.z * y0.z + y1.z * y1.z; cq.w += y0.w * y0.w + y1.w * y1.w;
    }

    *(float4*)&S1[wid * 128 + lane * 4] = cs;
    *(float4*)&S2[wid * 128 + lane * 4] = cq;
    __syncthreads();
    int tid = threadIdx.x;
    if (tid < 128) {
        float s = 0.f, q = 0.f;
        #pragma unroll
        for (int y = 0; y < 8; y++) { s += S1[y * 128 + tid]; q += S2[y * 128 + tid]; }
        atomicAdd(&g_sum[tid], s);
        atomicAdd(&g_sumsq[tid], q);
    }
}

// ---------------- K3: BN-finalize (per-warp) + apply + pooled segment sum ---
// OCHUNK=16 -> 782 blocks (6256 warps): grid-level MLP fix for latency bound.
#define OCHUNK 16
__global__ void __launch_bounds__(256)
k_out(const int* __restrict__ gid, const float* __restrict__ gamma,
      const float* __restrict__ beta, float* __restrict__ xout,
      float* __restrict__ phis) {
    int lane = threadIdx.x & 31;
    int wid  = threadIdx.x >> 5;
    int chunk = blockIdx.x * 8 + wid;
    int r0 = chunk * OCHUNK;
    if (r0 >= N_NODES) return;
    int rend = min(r0 + OCHUNK, N_NODES);

    // recompute scale/shift locally (tiny, L2-cached)
    float4 s1 = *(const float4*)&g_sum[lane * 4];
    float4 s2 = *(const float4*)&g_sumsq[lane * 4];
    float4 gm = __ldg(&((const float4*)gamma)[lane]);
    float4 bt = __ldg(&((const float4*)beta)[lane]);
    const float inv = 1.f / N_NODES;
    float4 sc, sh;
    {
        float m, v;
        m = s1.x * inv; v = s2.x * inv - m * m; sc.x = gm.x * rsqrtf(v + BN_EPS); sh.x = bt.x - m * sc.x;
        m = s1.y * inv; v = s2.y * inv - m * m; sc.y = gm.y * rsqrtf(v + BN_EPS); sh.y = bt.y - m * sc.y;
        m = s1.z * inv; v = s2.z * inv - m * m; sc.z = gm.z * rsqrtf(v + BN_EPS); sh.z = bt.z - m * sc.z;
        m = s1.w * inv; v = s2.w * inv - m * m; sc.w = gm.w * rsqrtf(v + BN_EPS); sh.w = bt.w - m * sc.w;
    }

    float4 acc = make_float4(0.f, 0.f, 0.f, 0.f);
    int gcur = __ldg(&gid[r0]);

    #pragma unroll 4
    for (int r = r0; r < rend; r++) {
        int g = __ldg(&gid[r]);
        uint2 q = ((const uint2*)(g_Y + (size_t)r * 64))[lane];
        float2 f0 = __half22float2(*(__half2*)&q.x);
        float2 f1 = __half22float2(*(__half2*)&q.y);
        float4 v;
        v.x = f0.x * sc.x + sh.x; v.y = f0.y * sc.y + sh.y;
        v.z = f1.x * sc.z + sh.z; v.w = f1.y * sc.w + sh.w;
        ((float4*)(xout + (size_t)r * FEAT))[lane] = v;
        if (g != gcur) {
            float* pp = phis + (size_t)gcur * FEAT + lane * 4;
            atomicAdd(pp + 0, acc.x); atomicAdd(pp + 1, acc.y);
            atomicAdd(pp + 2, acc.z); atomicAdd(pp + 3, acc.w);
            acc = make_float4(0.f, 0.f, 0.f, 0.f);
            gcur = g;
        }
        acc.x += v.x; acc.y += v.y; acc.z += v.z; acc.w += v.w;
    }
    float* pp = phis + (size_t)gcur * FEAT + lane * 4;
    atomicAdd(pp + 0, acc.x); atomicAdd(pp + 1, acc.y);
    atomicAdd(pp + 2, acc.z); atomicAdd(pp + 3, acc.w);
}

// ---------------- launch -----------------------------------------------------
extern "C" void kernel_launch(void* const* d_in, const int* in_sizes, int n_in,
                              void* d_out, int out_size) {
    const float* h     = (const float*)d_in[0];
    const float* norm  = (const float*)d_in[1];
    const float* W     = (const float*)d_in[2];
    const float* b     = (const float*)d_in[3];
    const float* gamma = (const float*)d_in[4];
    const float* beta  = (const float*)d_in[5];
    const int*   src   = (const int*)d_in[6];
    const int*   dst   = (const int*)d_in[7];
    const int*   gid   = (const int*)d_in[8];
    float* xout = (float*)d_out;
    float* phis = xout + (size_t)N_NODES * FEAT;

    const int smem_gemm = 2 * 128 * 128 * sizeof(float);   // 131072 B
    cudaFuncSetAttribute(k_gemm, cudaFuncAttributeMaxDynamicSharedMemorySize, smem_gemm);

    k_build<<<BUILD_BLKS, 256>>>(src, dst, phis);
    k_gemm<<<(N_NODES + 127) / 128, 256, smem_gemm>>>(h, norm, W);
    k_gather<<<GBLK, 256>>>(norm, b);
    k_out<<<(N_NODES + OCHUNK * 8 - 1) / (OCHUNK * 8), 256>>>(gid, gamma, beta, xout, phis);
}

// round 12
// speedup vs baseline: 1.3214x; 1.2088x over previous
#include <cuda_runtime.h>
#include <cuda_fp16.h>
#include <cstdint>

#define N_NODES 100000
#define N_EDGES 600000
#define FEAT    128
#define N_GRAPHS 100
#define BN_EPS  1e-5f
#define SLOTS   64

typedef unsigned long long ull;
typedef unsigned int uint;

// ---------------- scratch (device globals: no allocations allowed) ----------
__device__ uint  g_Z[(size_t)N_NODES * 64];       // Z = (h*norm)@W, half2-packed
__device__ float g_Y[(size_t)N_NODES * FEAT];     // post-relu activations (fp32)
__device__ int   g_cnt[N_NODES];                  // per-node in-degree
__device__ int   g_slot[(size_t)N_NODES * SLOTS]; // per-node src lists (padded)
__device__ float g_sum[FEAT];
__device__ float g_sumsq[FEAT];

// ---------------- helpers ---------------------------------------------------
__device__ __forceinline__ ull pk(float x) {
    ull r; asm("mov.b64 %0, {%1, %1};" : "=l"(r) : "f"(x)); return r;
}
__device__ __forceinline__ void ffma2(ull& d, ull a, ull b) {
    asm("fma.rn.f32x2 %0, %1, %2, %3;" : "=l"(d) : "l"(a), "l"(b), "l"(d));
}
__device__ __forceinline__ float2 up(ull v) {
    float2 p; asm("mov.b64 {%0, %1}, %2;" : "=f"(p.x), "=f"(p.y) : "l"(v)); return p;
}

// ---------------- K0: zero phis, BN accumulators, in-degree counters --------
#define NZERO (N_GRAPHS * FEAT + 2 * FEAT + N_NODES)
__global__ void k_zero(float* __restrict__ phis) {
    int i = blockIdx.x * blockDim.x + threadIdx.x;
    if (i < N_GRAPHS * FEAT)                  phis[i] = 0.f;
    else if (i < N_GRAPHS * FEAT + FEAT)      g_sum[i - N_GRAPHS * FEAT] = 0.f;
    else if (i < N_GRAPHS * FEAT + 2 * FEAT)  g_sumsq[i - N_GRAPHS * FEAT - FEAT] = 0.f;
    else if (i < NZERO)                       g_cnt[i - N_GRAPHS * FEAT - 2 * FEAT] = 0;
}

// ---------------- K1: build per-node src lists ------------------------------
__global__ void k_build(const int* __restrict__ src, const int* __restrict__ dst) {
    int e = blockIdx.x * blockDim.x + threadIdx.x;
    if (e >= N_EDGES) return;
    int d = __ldg(&dst[e]);
    int s = __ldg(&src[e]);
    int pos = atomicAdd(&g_cnt[d], 1);
    g_slot[(size_t)d * SLOTS + pos] = s;
}

// ---------------- K2: Z = (h*norm) @ W  (fp16 output, f32x2 FMA) ------------
// 256 threads = 8 warps. Tile 128x128, K=128 full.
// Warp w: cols 16w..16w+15 (broadcast W). Lane l: rows 4l..4l+3.
__global__ void __launch_bounds__(256, 1)
k_gemm(const float* __restrict__ h, const float* __restrict__ norm,
       const float* __restrict__ Wg) {
    extern __shared__ float sm[];
    float* As = sm;             // [k][m], stride 128
    float* Ws = sm + 16384;     // [k][c], stride 128
    int tid = threadIdx.x;
    int rowbase = blockIdx.x * 128;

    {
        int r = tid & 127, half = tid >> 7;
        int gr = rowbase + r;
        bool ok = (gr < N_NODES);
        float nm = ok ? __ldg(&norm[gr]) : 0.f;
        const float4* arow = (const float4*)(h + (size_t)gr * FEAT);
        #pragma unroll
        for (int j = 0; j < 16; j++) {
            int k = half * 64 + j * 4;
            float4 v = ok ? __ldg(&arow[k >> 2]) : make_float4(0.f, 0.f, 0.f, 0.f);
            As[(k + 0) * 128 + r] = v.x * nm;
            As[(k + 1) * 128 + r] = v.y * nm;
            As[(k + 2) * 128 + r] = v.z * nm;
            As[(k + 3) * 128 + r] = v.w * nm;
        }
    }
    #pragma unroll
    for (int it = 0; it < 16; it++) {
        int g = tid + 256 * it;            // float4 index, 4096 total
        int k = g >> 5, c = (g & 31) * 4;
        *(float4*)&Ws[k * 128 + c] = __ldg(&((const float4*)Wg)[g]);
    }
    __syncthreads();

    int w = tid >> 5, lane = tid & 31;
    int c0 = w * 16, r0 = lane * 4;

    ull acc[32];
    #pragma unroll
    for (int i = 0; i < 32; i++) acc[i] = 0ull;

    #pragma unroll 4
    for (int k = 0; k < 128; k++) {
        float4 av = *(const float4*)&As[k * 128 + r0];
        ull ad[4] = {pk(av.x), pk(av.y), pk(av.z), pk(av.w)};
        const ull* wp = (const ull*)&Ws[k * 128 + c0];
        ull wd[8];
        #pragma unroll
        for (int c2 = 0; c2 < 8; c2++) wd[c2] = wp[c2];
        #pragma unroll
        for (int r = 0; r < 4; r++)
            #pragma unroll
            for (int c2 = 0; c2 < 8; c2++)
                ffma2(acc[r * 8 + c2], ad[r], wd[c2]);
    }

    // store Z rows as half2
    #pragma unroll
    for (int r = 0; r < 4; r++) {
        int row = rowbase + r0 + r;
        if (row < N_NODES) {
            uint st[8];
            #pragma unroll
            for (int c2 = 0; c2 < 8; c2++) {
                float2 p = up(acc[r * 8 + c2]);
                __half2 hv = __floats2half2_rn(p.x, p.y);   // low = even col
                st[c2] = *(uint*)&hv;
            }
            uint* zr = g_Z + (size_t)row * 64 + c0 / 2;
            ((uint4*)zr)[0] = make_uint4(st[0], st[1], st[2], st[3]);
            ((uint4*)zr)[1] = make_uint4(st[4], st[5], st[6], st[7]);
        }
    }
}

// ---------------- K3: Y[v] = relu(norm[v]*sum_nbr Z[s] + b), BN stats -------
// One warp handles a PAIR of nodes; occupancy forced to 6 CTAs/SM.
#define GBLK 2048
__device__ __forceinline__ void acc_z(float4& a, int s, int lane) {
    uint2 q = __ldg(&((const uint2*)(g_Z + (size_t)s * 64))[lane]);
    float2 f0 = __half22float2(*(__half2*)&q.x);
    float2 f1 = __half22float2(*(__half2*)&q.y);
    a.x += f0.x; a.y += f0.y; a.z += f1.x; a.w += f1.y;
}
__global__ void __launch_bounds__(256, 6)
k_gather(const float* __restrict__ norm, const float* __restrict__ bg) {
    __shared__ float S1[8 * 128];
    __shared__ float S2[8 * 128];
    int lane = threadIdx.x & 31;
    int wid  = threadIdx.x >> 5;
    int gw   = blockIdx.x * 8 + wid;
    const int nw = GBLK * 8;

    float4 bv = __ldg(&((const float4*)bg)[lane]);
    float4 cs = make_float4(0.f, 0.f, 0.f, 0.f);
    float4 cq = make_float4(0.f, 0.f, 0.f, 0.f);

    for (int v0 = gw * 2; v0 < N_NODES; v0 += nw * 2) {
        int v1 = v0 + 1;                       // N_NODES even -> always valid
        int c0 = __ldg(&g_cnt[v0]), c1 = __ldg(&g_cnt[v1]);
        const int* sl0 = g_slot + (size_t)v0 * SLOTS;
        const int* sl1 = g_slot + (size_t)v1 * SLOTS;
        int ms0 = (lane < c0) ? __ldg(&sl0[lane]) : 0;
        int ms1 = (lane < c1) ? __ldg(&sl1[lane]) : 0;

        float4 a0 = make_float4(0.f, 0.f, 0.f, 0.f);
        float4 a1 = make_float4(0.f, 0.f, 0.f, 0.f);
        int cc0 = min(c0, 32), cc1 = min(c1, 32);
        int m = max(cc0, cc1);
        #pragma unroll 4
        for (int i = 0; i < m; i++) {
            if (i < cc0) { int s = __shfl_sync(0xffffffffu, ms0, i); acc_z(a0, s, lane); }
            if (i < cc1) { int s = __shfl_sync(0xffffffffu, ms1, i); acc_z(a1, s, lane); }
        }
        for (int i = 32; i < c0; i++) { int s = __ldg(&sl0[i]); acc_z(a0, s, lane); }
        for (int i = 32; i < c1; i++) { int s = __ldg(&sl1[i]); acc_z(a1, s, lane); }

        float n0 = __ldg(&norm[v0]);
        float n1 = __ldg(&norm[v1]);
        float4 y0, y1;
        y0.x = fmaxf(a0.x * n0 + bv.x, 0.f); y0.y = fmaxf(a0.y * n0 + bv.y, 0.f);
        y0.z = fmaxf(a0.z * n0 + bv.z, 0.f); y0.w = fmaxf(a0.w * n0 + bv.w, 0.f);
        y1.x = fmaxf(a1.x * n1 + bv.x, 0.f); y1.y = fmaxf(a1.y * n1 + bv.y, 0.f);
        y1.z = fmaxf(a1.z * n1 + bv.z, 0.f); y1.w = fmaxf(a1.w * n1 + bv.w, 0.f);
        ((float4*)(g_Y + (size_t)v0 * FEAT))[lane] = y0;
        ((float4*)(g_Y + (size_t)v1 * FEAT))[lane] = y1;
        cs.x += y0.x + y1.x; cs.y += y0.y + y1.y;
        cs.z += y0.z + y1.z; cs.w += y0.w + y1.w;
        cq.x += y0.x * y0.x + y1.x * y1.x; cq.y += y0.y * y0.y + y1.y * y1.y;
        cq.z += y0.z * y0.z + y1.z * y1.z; cq.w += y0.w * y0.w + y1.w * y1.w;
    }

    *(float4*)&S1[wid * 128 + lane * 4] = cs;
    *(float4*)&S2[wid * 128 + lane * 4] = cq;
    __syncthreads();
    int tid = threadIdx.x;
    if (tid < 128) {
        float s = 0.f, q = 0.f;
        #pragma unroll
        for (int y = 0; y < 8; y++) { s += S1[y * 128 + tid]; q += S2[y * 128 + tid]; }
        atomicAdd(&g_sum[tid], s);
        atomicAdd(&g_sumsq[tid], q);
    }
}

// ---------------- K4: BN-finalize (per-warp) + apply + pooled segment sum ---
// OCHUNK=16 -> 782 blocks: grid-level MLP (validated 35.5us -> 19.6us).
#define OCHUNK 16
__global__ void __launch_bounds__(256)
k_out(const int* __restrict__ gid, const float* __restrict__ gamma,
      const float* __restrict__ beta, float* __restrict__ xout,
      float* __restrict__ phis) {
    int lane = threadIdx.x & 31;
    int wid  = threadIdx.x >> 5;
    int chunk = blockIdx.x * 8 + wid;
    int r0 = chunk * OCHUNK;
    if (r0 >= N_NODES) return;
    int rend = min(r0 + OCHUNK, N_NODES);

    // recompute scale/shift locally (tiny, L2-cached)
    float4 s1 = *(const float4*)&g_sum[lane * 4];
    float4 s2 = *(const float4*)&g_sumsq[lane * 4];
    float4 gm = __ldg(&((const float4*)gamma)[lane]);
    float4 bt = __ldg(&((const float4*)beta)[lane]);
    const float inv = 1.f / N_NODES;
    float4 sc, sh;
    {
        float m, v;
        m = s1.x * inv; v = s2.x * inv - m * m; sc.x = gm.x * rsqrtf(v + BN_EPS); sh.x = bt.x - m * sc.x;
        m = s1.y * inv; v = s2.y * inv - m * m; sc.y = gm.y * rsqrtf(v + BN_EPS); sh.y = bt.y - m * sc.y;
        m = s1.z * inv; v = s2.z * inv - m * m; sc.z = gm.z * rsqrtf(v + BN_EPS); sh.z = bt.z - m * sc.z;
        m = s1.w * inv; v = s2.w * inv - m * m; sc.w = gm.w * rsqrtf(v + BN_EPS); sh.w = bt.w - m * sc.w;
    }

    float4 acc = make_float4(0.f, 0.f, 0.f, 0.f);
    int gcur = __ldg(&gid[r0]);

    #pragma unroll 4
    for (int r = r0; r < rend; r++) {
        int g = __ldg(&gid[r]);
        float4 y = ((const float4*)(g_Y + (size_t)r * FEAT))[lane];
        float4 v;
        v.x = y.x * sc.x + sh.x; v.y = y.y * sc.y + sh.y;
        v.z = y.z * sc.z + sh.z; v.w = y.w * sc.w + sh.w;
        ((float4*)(xout + (size_t)r * FEAT))[lane] = v;
        if (g != gcur) {
            float* pp = phis + (size_t)gcur * FEAT + lane * 4;
            atomicAdd(pp + 0, acc.x); atomicAdd(pp + 1, acc.y);
            atomicAdd(pp + 2, acc.z); atomicAdd(pp + 3, acc.w);
            acc = make_float4(0.f, 0.f, 0.f, 0.f);
            gcur = g;
        }
        acc.x += v.x; acc.y += v.y; acc.z += v.z; acc.w += v.w;
    }
    float* pp = phis + (size_t)gcur * FEAT + lane * 4;
    atomicAdd(pp + 0, acc.x); atomicAdd(pp + 1, acc.y);
    atomicAdd(pp + 2, acc.z); atomicAdd(pp + 3, acc.w);
}

// ---------------- launch -----------------------------------------------------
extern "C" void kernel_launch(void* const* d_in, const int* in_sizes, int n_in,
                              void* d_out, int out_size) {
    const float* h     = (const float*)d_in[0];
    const float* norm  = (const float*)d_in[1];
    const float* W     = (const float*)d_in[2];
    const float* b     = (const float*)d_in[3];
    const float* gamma = (const float*)d_in[4];
    const float* beta  = (const float*)d_in[5];
    const int*   src   = (const int*)d_in[6];
    const int*   dst   = (const int*)d_in[7];
    const int*   gid   = (const int*)d_in[8];
    float* xout = (float*)d_out;
    float* phis = xout + (size_t)N_NODES * FEAT;

    const int smem_gemm = 2 * 128 * 128 * sizeof(float);   // 131072 B
    cudaFuncSetAttribute(k_gemm, cudaFuncAttributeMaxDynamicSharedMemorySize, smem_gemm);

    k_zero<<<(NZERO + 255) / 256, 256>>>(phis);
    k_build<<<(N_EDGES + 255) / 256, 256>>>(src, dst);
    k_gemm<<<(N_NODES + 127) / 128, 256, smem_gemm>>>(h, norm, W);
    k_gather<<<GBLK, 256>>>(norm, b);
    k_out<<<(N_NODES + OCHUNK * 8 - 1) / (OCHUNK * 8), 256>>>(gid, gamma, beta, xout, phis);
}

// round 13
// speedup vs baseline: 1.3739x; 1.0397x over previous
#include <cuda_runtime.h>
#include <cuda_fp16.h>
#include <cstdint>

#define N_NODES 100000
#define N_EDGES 600000
#define FEAT    128
#define N_GRAPHS 100
#define BN_EPS  1e-5f
#define SLOTS   64

typedef unsigned long long ull;
typedef unsigned int uint;

// ---------------- scratch (device globals: no allocations allowed) ----------
// INVARIANT: g_cnt is all-zero at every kernel_launch entry (zero-init at
// module load; re-zeroed by k_out at the end of every call).
__device__ uint  g_Z[(size_t)N_NODES * 64];       // Z = (h*norm)@W, half2-packed
__device__ float g_Y[(size_t)N_NODES * FEAT];     // post-relu activations (fp32)
__device__ int   g_cnt[N_NODES];                  // per-node in-degree
__device__ int   g_slot[(size_t)N_NODES * SLOTS]; // per-node src lists (padded)
__device__ float g_sum[FEAT];
__device__ float g_sumsq[FEAT];

// ---------------- helpers ---------------------------------------------------
__device__ __forceinline__ ull pk(float x) {
    ull r; asm("mov.b64 %0, {%1, %1};" : "=l"(r) : "f"(x)); return r;
}
__device__ __forceinline__ void ffma2(ull& d, ull a, ull b) {
    asm("fma.rn.f32x2 %0, %1, %2, %3;" : "=l"(d) : "l"(a), "l"(b), "l"(d));
}
__device__ __forceinline__ float2 up(ull v) {
    float2 p; asm("mov.b64 {%0, %1}, %2;" : "=f"(p.x), "=f"(p.y) : "l"(v)); return p;
}

// ---------------- K1: build per-node src lists (+ fused phis/BN zeroing) ----
// Flat: one edge per thread, 2344 blocks. Blocks 0..50 also zero the 13056
// floats of phis/g_sum/g_sumsq (write-only, no interference with edge work).
#define NZERO2 (N_GRAPHS * FEAT + 2 * FEAT)   // 13056
__global__ void k_build(const int* __restrict__ src, const int* __restrict__ dst,
                        float* __restrict__ phis) {
    int i = blockIdx.x * blockDim.x + threadIdx.x;
    if (i < NZERO2) {
        if (i < N_GRAPHS * FEAT)           phis[i] = 0.f;
        else if (i < N_GRAPHS * FEAT + FEAT) g_sum[i - N_GRAPHS * FEAT] = 0.f;
        else                               g_sumsq[i - N_GRAPHS * FEAT - FEAT] = 0.f;
    }
    if (i >= N_EDGES) return;
    int d = __ldg(&dst[i]);
    int s = __ldg(&src[i]);
    int pos = atomicAdd(&g_cnt[d], 1);
    g_slot[(size_t)d * SLOTS + pos] = s;
}

// ---------------- K2: Z = (h*norm) @ W  (fp16 output, f32x2 FMA) ------------
// 256 threads = 8 warps. Tile 128x128, K=128 full.
// Warp w: cols 16w..16w+15 (broadcast W). Lane l: rows 4l..4l+3.
__global__ void __launch_bounds__(256, 1)
k_gemm(const float* __restrict__ h, const float* __restrict__ norm,
       const float* __restrict__ Wg) {
    extern __shared__ float sm[];
    float* As = sm;             // [k][m], stride 128
    float* Ws = sm + 16384;     // [k][c], stride 128
    int tid = threadIdx.x;
    int rowbase = blockIdx.x * 128;

    {
        int r = tid & 127, half = tid >> 7;
        int gr = rowbase + r;
        bool ok = (gr < N_NODES);
        float nm = ok ? __ldg(&norm[gr]) : 0.f;
        const float4* arow = (const float4*)(h + (size_t)gr * FEAT);
        #pragma unroll
        for (int j = 0; j < 16; j++) {
            int k = half * 64 + j * 4;
            float4 v = ok ? __ldg(&arow[k >> 2]) : make_float4(0.f, 0.f, 0.f, 0.f);
            As[(k + 0) * 128 + r] = v.x * nm;
            As[(k + 1) * 128 + r] = v.y * nm;
            As[(k + 2) * 128 + r] = v.z * nm;
            As[(k + 3) * 128 + r] = v.w * nm;
        }
    }
    #pragma unroll
    for (int it = 0; it < 16; it++) {
        int g = tid + 256 * it;            // float4 index, 4096 total
        int k = g >> 5, c = (g & 31) * 4;
        *(float4*)&Ws[k * 128 + c] = __ldg(&((const float4*)Wg)[g]);
    }
    __syncthreads();

    int w = tid >> 5, lane = tid & 31;
    int c0 = w * 16, r0 = lane * 4;

    ull acc[32];
    #pragma unroll
    for (int i = 0; i < 32; i++) acc[i] = 0ull;

    #pragma unroll 4
    for (int k = 0; k < 128; k++) {
        float4 av = *(const float4*)&As[k * 128 + r0];
        ull ad[4] = {pk(av.x), pk(av.y), pk(av.z), pk(av.w)};
        const ull* wp = (const ull*)&Ws[k * 128 + c0];
        ull wd[8];
        #pragma unroll
        for (int c2 = 0; c2 < 8; c2++) wd[c2] = wp[c2];
        #pragma unroll
        for (int r = 0; r < 4; r++)
            #pragma unroll
            for (int c2 = 0; c2 < 8; c2++)
                ffma2(acc[r * 8 + c2], ad[r], wd[c2]);
    }

    // store Z rows as half2
    #pragma unroll
    for (int r = 0; r < 4; r++) {
        int row = rowbase + r0 + r;
        if (row < N_NODES) {
            uint st[8];
            #pragma unroll
            for (int c2 = 0; c2 < 8; c2++) {
                float2 p = up(acc[r * 8 + c2]);
                __half2 hv = __floats2half2_rn(p.x, p.y);   // low = even col
                st[c2] = *(uint*)&hv;
            }
            uint* zr = g_Z + (size_t)row * 64 + c0 / 2;
            ((uint4*)zr)[0] = make_uint4(st[0], st[1], st[2], st[3]);
            ((uint4*)zr)[1] = make_uint4(st[4], st[5], st[6], st[7]);
        }
    }
}

// ---------------- K3: Y[v] = relu(norm[v]*sum_nbr Z[s] + b), BN stats -------
// One warp handles a PAIR of nodes (R12-exact; NO g_cnt writes here).
#define GBLK 2048
__device__ __forceinline__ void acc_z(float4& a, int s, int lane) {
    uint2 q = __ldg(&((const uint2*)(g_Z + (size_t)s * 64))[lane]);
    float2 f0 = __half22float2(*(__half2*)&q.x);
    float2 f1 = __half22float2(*(__half2*)&q.y);
    a.x += f0.x; a.y += f0.y; a.z += f1.x; a.w += f1.y;
}
__global__ void __launch_bounds__(256, 6)
k_gather(const float* __restrict__ norm, const float* __restrict__ bg) {
    __shared__ float S1[8 * 128];
    __shared__ float S2[8 * 128];
    int lane = threadIdx.x & 31;
    int wid  = threadIdx.x >> 5;
    int gw   = blockIdx.x * 8 + wid;
    const int nw = GBLK * 8;

    float4 bv = __ldg(&((const float4*)bg)[lane]);
    float4 cs = make_float4(0.f, 0.f, 0.f, 0.f);
    float4 cq = make_float4(0.f, 0.f, 0.f, 0.f);

    for (int v0 = gw * 2; v0 < N_NODES; v0 += nw * 2) {
        int v1 = v0 + 1;                       // N_NODES even -> always valid
        int c0 = __ldg(&g_cnt[v0]), c1 = __ldg(&g_cnt[v1]);
        const int* sl0 = g_slot + (size_t)v0 * SLOTS;
        const int* sl1 = g_slot + (size_t)v1 * SLOTS;
        int ms0 = (lane < c0) ? __ldg(&sl0[lane]) : 0;
        int ms1 = (lane < c1) ? __ldg(&sl1[lane]) : 0;

        float4 a0 = make_float4(0.f, 0.f, 0.f, 0.f);
        float4 a1 = make_float4(0.f, 0.f, 0.f, 0.f);
        int cc0 = min(c0, 32), cc1 = min(c1, 32);
        int m = max(cc0, cc1);
        #pragma unroll 4
        for (int i = 0; i < m; i++) {
            if (i < cc0) { int s = __shfl_sync(0xffffffffu, ms0, i); acc_z(a0, s, lane); }
            if (i < cc1) { int s = __shfl_sync(0xffffffffu, ms1, i); acc_z(a1, s, lane); }
        }
        for (int i = 32; i < c0; i++) { int s = __ldg(&sl0[i]); acc_z(a0, s, lane); }
        for (int i = 32; i < c1; i++) { int s = __ldg(&sl1[i]); acc_z(a1, s, lane); }

        float n0 = __ldg(&norm[v0]);
        float n1 = __ldg(&norm[v1]);
        float4 y0, y1;
        y0.x = fmaxf(a0.x * n0 + bv.x, 0.f); y0.y = fmaxf(a0.y * n0 + bv.y, 0.f);
        y0.z = fmaxf(a0.z * n0 + bv.z, 0.f); y0.w = fmaxf(a0.w * n0 + bv.w, 0.f);
        y1.x = fmaxf(a1.x * n1 + bv.x, 0.f); y1.y = fmaxf(a1.y * n1 + bv.y, 0.f);
        y1.z = fmaxf(a1.z * n1 + bv.z, 0.f); y1.w = fmaxf(a1.w * n1 + bv.w, 0.f);
        ((float4*)(g_Y + (size_t)v0 * FEAT))[lane] = y0;
        ((float4*)(g_Y + (size_t)v1 * FEAT))[lane] = y1;
        cs.x += y0.x + y1.x; cs.y += y0.y + y1.y;
        cs.z += y0.z + y1.z; cs.w += y0.w + y1.w;
        cq.x += y0.x * y0.x + y1.x * y1.x; cq.y += y0.y * y0.y + y1.y * y1.y;
        cq.z += y0.z * y0.z + y1.z * y1.z; cq.w += y0.w * y0.w + y1.w * y1.w;
    }

    *(float4*)&S1[wid * 128 + lane * 4] = cs;
    *(float4*)&S2[wid * 128 + lane * 4] = cq;
    __syncthreads();
    int tid = threadIdx.x;
    if (tid < 128) {
        float s = 0.f, q = 0.f;
        #pragma unroll
        for (int y = 0; y < 8; y++) { s += S1[y * 128 + tid]; q += S2[y * 128 + tid]; }
        atomicAdd(&g_sum[tid], s);
        atomicAdd(&g_sumsq[tid], q);
    }
}

// ---------------- K4: BN-finalize + apply + pooled segment sum + cnt reset --
// OCHUNK=16 -> 782 blocks (validated). Also re-zeroes g_cnt (runs after
// gather has consumed it -> no read/write interference; coalesced).
#define OCHUNK 16
__global__ void __launch_bounds__(256)
k_out(const int* __restrict__ gid, const float* __restrict__ gamma,
      const float* __restrict__ beta, float* __restrict__ xout,
      float* __restrict__ phis) {
    // g_cnt reset for next call (before any early return; 782*256 >= N_NODES)
    {
        int i = blockIdx.x * 256 + threadIdx.x;
        if (i < N_NODES) g_cnt[i] = 0;
    }
    int lane = threadIdx.x & 31;
    int wid  = threadIdx.x >> 5;
    int chunk = blockIdx.x * 8 + wid;
    int r0 = chunk * OCHUNK;
    if (r0 >= N_NODES) return;
    int rend = min(r0 + OCHUNK, N_NODES);

    // recompute scale/shift locally (tiny, L2-cached)
    float4 s1 = *(const float4*)&g_sum[lane * 4];
    float4 s2 = *(const float4*)&g_sumsq[lane * 4];
    float4 gm = __ldg(&((const float4*)gamma)[lane]);
    float4 bt = __ldg(&((const float4*)beta)[lane]);
    const float inv = 1.f / N_NODES;
    float4 sc, sh;
    {
        float m, v;
        m = s1.x * inv; v = s2.x * inv - m * m; sc.x = gm.x * rsqrtf(v + BN_EPS); sh.x = bt.x - m * sc.x;
        m = s1.y * inv; v = s2.y * inv - m * m; sc.y = gm.y * rsqrtf(v + BN_EPS); sh.y = bt.y - m * sc.y;
        m = s1.z * inv; v = s2.z * inv - m * m; sc.z = gm.z * rsqrtf(v + BN_EPS); sh.z = bt.z - m * sc.z;
        m = s1.w * inv; v = s2.w * inv - m * m; sc.w = gm.w * rsqrtf(v + BN_EPS); sh.w = bt.w - m * sc.w;
    }

    float4 acc = make_float4(0.f, 0.f, 0.f, 0.f);
    int gcur = __ldg(&gid[r0]);

    #pragma unroll 4
    for (int r = r0; r < rend; r++) {
        int g = __ldg(&gid[r]);
        float4 y = ((const float4*)(g_Y + (size_t)r * FEAT))[lane];
        float4 v;
        v.x = y.x * sc.x + sh.x; v.y = y.y * sc.y + sh.y;
        v.z = y.z * sc.z + sh.z; v.w = y.w * sc.w + sh.w;
        ((float4*)(xout + (size_t)r * FEAT))[lane] = v;
        if (g != gcur) {
            float* pp = phis + (size_t)gcur * FEAT + lane * 4;
            atomicAdd(pp + 0, acc.x); atomicAdd(pp + 1, acc.y);
            atomicAdd(pp + 2, acc.z); atomicAdd(pp + 3, acc.w);
            acc = make_float4(0.f, 0.f, 0.f, 0.f);
            gcur = g;
        }
        acc.x += v.x; acc.y += v.y; acc.z += v.z; acc.w += v.w;
    }
    float* pp = phis + (size_t)gcur * FEAT + lane * 4;
    atomicAdd(pp + 0, acc.x); atomicAdd(pp + 1, acc.y);
    atomicAdd(pp + 2, acc.z); atomicAdd(pp + 3, acc.w);
}

// ---------------- launch -----------------------------------------------------
extern "C" void kernel_launch(void* const* d_in, const int* in_sizes, int n_in,
                              void* d_out, int out_size) {
    const float* h     = (const float*)d_in[0];
    const float* norm  = (const float*)d_in[1];
    const float* W     = (const float*)d_in[2];
    const float* b     = (const float*)d_in[3];
    const float* gamma = (const float*)d_in[4];
    const float* beta  = (const float*)d_in[5];
    const int*   src   = (const int*)d_in[6];
    const int*   dst   = (const int*)d_in[7];
    const int*   gid   = (const int*)d_in[8];
    float* xout = (float*)d_out;
    float* phis = xout + (size_t)N_NODES * FEAT;

    const int smem_gemm = 2 * 128 * 128 * sizeof(float);   // 131072 B
    cudaFuncSetAttribute(k_gemm, cudaFuncAttributeMaxDynamicSharedMemorySize, smem_gemm);

    k_build<<<(N_EDGES + 255) / 256, 256>>>(src, dst, phis);
    k_gemm<<<(N_NODES + 127) / 128, 256, smem_gemm>>>(h, norm, W);
    k_gather<<<GBLK, 256>>>(norm, b);
    k_out<<<(N_NODES + OCHUNK * 8 - 1) / (OCHUNK * 8), 256>>>(gid, gamma, beta, xout, phis);
}